// round 12
// baseline (speedup 1.0000x reference)
#include <cuda_runtime.h>
#include <cstdint>

// ---------------------------------------------------------------------------
// QuadConv via baseline-PTX tf32 mma.sync + ldmatrix (virtual arch compute_103).
//
//   out[N,128] = concat_k( F[idx[:,k]] ) @ W^T + b
//   N=262144, C_IN=C_OUT=128, K=9 -> GEMM M=N, N=128, K=1152 (A row-gathered).
//   neigh_idx is int32 on the wire.
//
// R11: per-CTA K-phase rotation. Tensor-busy wall time is a fixed 255us
// across all configs (fallback HMMA floor); wall = 255 / tensor_fraction.
// Co-resident CTAs (bids spaced ~148, 148%3==1) run identical code in
// lock-step -> load/barrier bursts collide and the tensor pipe drains in
// unison. Rotating each CTA's k-block start by (blockIdx%3)*12 interleaves
// one CTA's load phase with its partners' mma phases. Same GEMM, permuted
// fp32 accumulation order. Base config = R10 (3 CTAs/SM, 2x2 warps 64x64,
// lazy B, reg-cached indices, +0x1000 RNA trick).
// ---------------------------------------------------------------------------

namespace qc {
constexpr int NPTS   = 262144;
constexpr int CIN    = 128;
constexpr int COUT   = 128;
constexpr int KNB    = 9;
constexpr int KTOT   = KNB * CIN;      // 1152
constexpr int NKB    = KTOT / 32;      // 36 k-blocks of 32
constexpr int MTILE  = 128;
constexpr int CTAS   = NPTS / MTILE;   // 2048
constexpr int THREADS = 128;           // 4 warps

constexpr int ROWPAD = 36;             // 32 + 4 pad; conflict-free ldmatrix
constexpr int A_FLOATS   = MTILE * ROWPAD;      // 4608 per buffer
constexpr int B_FLOATS   = COUT * ROWPAD;       // 4608 per buffer
constexpr int OFF_A      = 0;                   // 2 buffers
constexpr int OFF_B      = 2 * A_FLOATS;        // 2 buffers
constexpr int SMEM_FLOATS = OFF_B + 2 * B_FLOATS;   // 18432
constexpr int SMEM_BYTES  = SMEM_FLOATS * 4;        // 73,728 -> 3 CTAs/SM
} // namespace qc

// W pre-converted to tf32 (RNA) once per launch. Static device scratch.
__device__ uint32_t W_TF32[qc::COUT * qc::KTOT];

// ------------------------------ PTX helpers -------------------------------

__device__ __forceinline__ uint32_t smem_u32(const void* p) {
    return (uint32_t)__cvta_generic_to_shared(p);
}

__device__ __forceinline__ void cp_async16(uint32_t dst, const void* src, int src_size) {
    asm volatile("cp.async.cg.shared.global [%0], [%1], 16, %2;"
                 ::"r"(dst), "l"(src), "r"(src_size) : "memory");
}
__device__ __forceinline__ void cp_commit() {
    asm volatile("cp.async.commit_group;" ::: "memory");
}
template <int N>
__device__ __forceinline__ void cp_wait() {
    asm volatile("cp.async.wait_group %0;" ::"n"(N) : "memory");
}

__device__ __forceinline__ uint32_t f2tf32(float f) {
    uint32_t u;
    asm("cvt.rna.tf32.f32 %0, %1;" : "=r"(u) : "f"(f));
    return u;
}

__device__ __forceinline__ void ldmatrix_x4(uint32_t& r0, uint32_t& r1,
                                            uint32_t& r2, uint32_t& r3, uint32_t addr) {
    asm volatile("ldmatrix.sync.aligned.m8n8.x4.shared.b16 {%0,%1,%2,%3}, [%4];"
                 : "=r"(r0), "=r"(r1), "=r"(r2), "=r"(r3) : "r"(addr));
}

__device__ __forceinline__ void mma_tf32(float& c0, float& c1, float& c2, float& c3,
                                         uint32_t a0, uint32_t a1, uint32_t a2, uint32_t a3,
                                         uint32_t b0, uint32_t b1) {
    asm volatile(
        "mma.sync.aligned.m16n8k8.row.col.f32.tf32.tf32.f32 "
        "{%0,%1,%2,%3}, {%4,%5,%6,%7}, {%8,%9}, {%0,%1,%2,%3};"
        : "+f"(c0), "+f"(c1), "+f"(c2), "+f"(c3)
        : "r"(a0), "r"(a1), "r"(a2), "r"(a3), "r"(b0), "r"(b1));
}

// ----------------------- pre-kernel: W -> tf32 -----------------------------

__global__ void wconv_kernel(const float* __restrict__ W) {
    int i = blockIdx.x * 256 + threadIdx.x;
    if (i < qc::COUT * qc::KTOT) W_TF32[i] = f2tf32(W[i]);
}

// ------------------------------- kernel -----------------------------------

__global__ void __launch_bounds__(qc::THREADS, 3)
quadconv_mma_kernel(const float* __restrict__ F,
                    const int* __restrict__ NIDX,
                    const float* __restrict__ BIAS,
                    float* __restrict__ OUT) {
    using namespace qc;
    extern __shared__ float sm[];
    const uint32_t sA_u = smem_u32(sm + OFF_A);
    const uint32_t sB_u = smem_u32(sm + OFF_B);

    const int tid  = threadIdx.x;
    const int wid  = tid >> 5;    // 0..3
    const int lane = tid & 31;
    const int g    = lane >> 2;   // 0..7
    const int klo  = lane & 3;    // 0..3
    const int gb   = blockIdx.x * MTILE;

    // K-phase rotation: co-resident CTAs (bid spacing ~148, 148%3==1) get
    // rotations 0/12/24 -> phases decorrelate.
    const int rot = (blockIdx.x % 3) * 12;

    // ---- per-thread loader coordinates & register-cached indices -----------
    const int lrow = tid >> 3;    // 0..15
    const int lseg = tid & 7;     // 0..7
    int idxr[8];                  // neighbor index for rows lrow+16i, current kn
    auto refresh_idx = [&](int kn) {
#pragma unroll
        for (int i = 0; i < 8; i++)
            idxr[i] = NIDX[(size_t)(gb + lrow + i * 16) * KNB + kn];
    };

    // A gather (zfill OOB, raw fp32) + B (pre-converted tf32 W chunk).
    // caller guarantees idxr matches kb>>2.
    auto load_tiles = [&](int kb, int buf) {
        const int coff = (kb & 3) * 32;
#pragma unroll
        for (int i = 0; i < 8; i++) {          // A: 1024 chunks / 128 thr
            int row = lrow + i * 16;
            int nb  = idxr[i];
            bool ok = (unsigned)nb < (unsigned)NPTS;
            const float* src = F + (size_t)(ok ? nb : 0) * CIN + coff + lseg * 4;
            cp_async16(sA_u + (uint32_t)(buf * A_FLOATS + row * ROWPAD + lseg * 4) * 4,
                       src, ok ? 16 : 0);
        }
#pragma unroll
        for (int i = 0; i < 8; i++) {          // B: 1024 chunks / 128 thr
            int n = lrow + i * 16;
            const uint32_t* src = W_TF32 + (size_t)n * KTOT + kb * 32 + lseg * 4;
            cp_async16(sB_u + (uint32_t)(buf * B_FLOATS + n * ROWPAD + lseg * 4) * 4,
                       src, 16);
        }
    };

    // ---- warp tiling: 4 warps 2x2, warp tile 64(M) x 64(N) -----------------
    const int Mbase = (wid >> 1) * 64;
    const int Nbase = (wid & 1) * 64;
    float acc[4][8][4];
#pragma unroll
    for (int mf = 0; mf < 4; mf++)
#pragma unroll
        for (int nf = 0; nf < 8; nf++)
#pragma unroll
            for (int q = 0; q < 4; q++) acc[mf][nf][q] = 0.f;

    // ---- ldmatrix per-lane base offsets (bytes, buffer-relative) -----------
    const int a_rit = (lane & 7) + ((lane >> 3) & 1) * 8;
    const int a_k4  = (lane >> 4) * 4;
    uint32_t aoff[4];
#pragma unroll
    for (int mf = 0; mf < 4; mf++)
        aoff[mf] = (uint32_t)(((Mbase + mf * 16 + a_rit) * ROWPAD + a_k4) * 4);
    const int b_nr = ((lane >> 4) & 1) * 8 + (lane & 7);
    const int b_k4 = ((lane >> 3) & 1) * 4;
    uint32_t boff[4];
#pragma unroll
    for (int p = 0; p < 4; p++)
        boff[p] = (uint32_t)(((Nbase + p * 16 + b_nr) * ROWPAD + b_k4) * 4);

    // ---- prologue: first (rotated) k-block ----------------------------------
    int kn_cur = rot >> 2;
    refresh_idx(kn_cur);
    load_tiles(rot, 0);
    cp_commit();

    // ---- main K loop (rotated order; loads first, then wait, then mma) ------
    for (int i = 0; i < NKB; i++) {
        const int buf = i & 1;
        if (i + 1 < NKB) {
            int kbp = rot + i + 1;
            if (kbp >= NKB) kbp -= NKB;
            const int knp = kbp >> 2;
            if (knp != kn_cur) { kn_cur = knp; refresh_idx(knp); }
            load_tiles(kbp, buf ^ 1);
            cp_commit();
            cp_wait<1>();
        } else {
            cp_wait<0>();
        }
        __syncthreads();   // cross-thread visibility of buf's tiles

        const uint32_t abuf = sA_u + (uint32_t)(buf * A_FLOATS) * 4;
        const uint32_t bbuf = sB_u + (uint32_t)(buf * B_FLOATS) * 4;

#pragma unroll
        for (int s = 0; s < 4; s++) {          // 4 k-steps of 8
            uint32_t afr[4][4];
#pragma unroll
            for (int mf = 0; mf < 4; mf++)
                ldmatrix_x4(afr[mf][0], afr[mf][1], afr[mf][2], afr[mf][3],
                            abuf + aoff[mf] + s * 32);
            // RNA-to-tf32 on raw fp32 A fragments (+0x1000; HW drops low 13b)
#pragma unroll
            for (int mf = 0; mf < 4; mf++) {
                afr[mf][0] += 0x1000u; afr[mf][1] += 0x1000u;
                afr[mf][2] += 0x1000u; afr[mf][3] += 0x1000u;
            }
            // lazy B: one ldmatrix per nf-pair, immediately consumed
#pragma unroll
            for (int p = 0; p < 4; p++) {
                uint32_t b0a, b0b, b1a, b1b;
                ldmatrix_x4(b0a, b0b, b1a, b1b, bbuf + boff[p] + s * 32);
#pragma unroll
                for (int mf = 0; mf < 4; mf++) {
                    mma_tf32(acc[mf][2 * p][0], acc[mf][2 * p][1],
                             acc[mf][2 * p][2], acc[mf][2 * p][3],
                             afr[mf][0], afr[mf][1], afr[mf][2], afr[mf][3],
                             b0a, b0b);
                    mma_tf32(acc[mf][2 * p + 1][0], acc[mf][2 * p + 1][1],
                             acc[mf][2 * p + 1][2], acc[mf][2 * p + 1][3],
                             afr[mf][0], afr[mf][1], afr[mf][2], afr[mf][3],
                             b1a, b1b);
                }
            }
        }
        __syncthreads();   // all reads of buf done before i+2 overwrites it
    }

    // ---- epilogue: add bias (global, L2-hot), float2 stores -----------------
#pragma unroll
    for (int mf = 0; mf < 4; mf++) {
#pragma unroll
        for (int nf = 0; nf < 8; nf++) {
            int col  = Nbase + nf * 8 + 2 * klo;
            float bx = __ldg(BIAS + col), by = __ldg(BIAS + col + 1);
            size_t r0 = (size_t)(gb + Mbase + mf * 16 + g) * COUT + col;
            size_t r1 = r0 + (size_t)8 * COUT;
            float2 v0 = make_float2(acc[mf][nf][0] + bx, acc[mf][nf][1] + by);
            float2 v1 = make_float2(acc[mf][nf][2] + bx, acc[mf][nf][3] + by);
            *(float2*)(OUT + r0) = v0;
            *(float2*)(OUT + r1) = v1;
        }
    }
}

// ----------------------------- launch glue --------------------------------

extern "C" void kernel_launch(void* const* d_in, const int* in_sizes, int n_in,
                              void* d_out, int out_size) {
    using namespace qc;
    const float* F = (const float*)d_in[0];
    const int*   I = (const int*)d_in[1];
    const float* W = (const float*)d_in[2];
    const float* B = (const float*)d_in[3];
    for (int i = 0; i < n_in; i++) {
        switch (in_sizes[i]) {
            case NPTS * CIN:       F = (const float*)d_in[i]; break;      // 33554432
            case NPTS * KNB:       I = (const int*)d_in[i];   break;      // 2359296
            case COUT * KNB * CIN: W = (const float*)d_in[i]; break;      // 147456
            case COUT:             B = (const float*)d_in[i]; break;      // 128
            default: break;
        }
    }
    wconv_kernel<<<(COUT * KTOT + 255) / 256, 256>>>(W);
    cudaFuncSetAttribute(quadconv_mma_kernel,
                         cudaFuncAttributeMaxDynamicSharedMemorySize, SMEM_BYTES);
    quadconv_mma_kernel<<<CTAS, THREADS, SMEM_BYTES>>>(F, I, B, (float*)d_out);
}

// round 14
// speedup vs baseline: 1.4886x; 1.4886x over previous
#include <cuda_runtime.h>
#include <cuda_fp16.h>
#include <cstdint>

// ---------------------------------------------------------------------------
// QuadConv via baseline-PTX fp16 mma.sync m16n8k16 + ldmatrix (compute_103).
//
//   out[N,128] = concat_k( F[idx[:,k]] ) @ W^T + b
//   N=262144, C_IN=C_OUT=128, K=9 -> GEMM M=N, N=128, K=1152 (A row-gathered).
//   neigh_idx is int32 on the wire.
//
// R13 (= R12 with the compile fix): tf32 -> fp16. fp16 and tf32 both have 10
// mantissa bits -> identical rounding error (rel_err ~2.9e-4), but m16n8k16
// does 2x MACs per HMMA -> tensor floor 255us -> ~128us. F and W are
// pre-converted to fp16 once per launch (also halves gather traffic); the
// main loop has ZERO conversion work: cp.async fp16 tiles, ldmatrix, HMMA.
// Base config = R10 (3 CTAs/SM, 4 warps 2x2, warp tile 64x64, lazy B,
// reg-cached indices; no K rotation — R11 showed it regresses).
// ---------------------------------------------------------------------------

namespace qc {
constexpr int NPTS   = 262144;
constexpr int CIN    = 128;
constexpr int COUT   = 128;
constexpr int KNB    = 9;
constexpr int KTOT   = KNB * CIN;      // 1152
constexpr int NKB    = KTOT / 32;      // 36 k-blocks of 32
constexpr int MTILE  = 128;
constexpr int CTAS   = NPTS / MTILE;   // 2048
constexpr int THREADS = 128;           // 4 warps

constexpr int ROWPAD = 40;             // halves per smem row (32 + 8 pad = 80B)
                                       // ldmatrix phase banks: 20r mod 32 distinct
constexpr int A_HALF = MTILE * ROWPAD;          // 5120 halves per buffer
constexpr int B_HALF = COUT * ROWPAD;           // 5120
constexpr int OFF_A  = 0;                       // 2 buffers
constexpr int OFF_B  = 2 * A_HALF;              // 2 buffers
constexpr int SMEM_HALVES = OFF_B + 2 * B_HALF; // 20480
constexpr int SMEM_BYTES  = SMEM_HALVES * 2;    // 40,960
} // namespace qc

// fp16 copies of F and W, produced once per launch by pre-kernels.
__device__ __half F16[qc::NPTS * qc::CIN];      // 64 MB static
__device__ __half W16[qc::COUT * qc::KTOT];     // 288 KB static

// ------------------------------ PTX helpers -------------------------------

__device__ __forceinline__ uint32_t smem_u32(const void* p) {
    return (uint32_t)__cvta_generic_to_shared(p);
}

__device__ __forceinline__ uint32_t h2_as_u32(__half2 h) {
    uint32_t u;
    memcpy(&u, &h, 4);
    return u;
}

__device__ __forceinline__ void cp_async16(uint32_t dst, const void* src, int src_size) {
    asm volatile("cp.async.cg.shared.global [%0], [%1], 16, %2;"
                 ::"r"(dst), "l"(src), "r"(src_size) : "memory");
}
__device__ __forceinline__ void cp_commit() {
    asm volatile("cp.async.commit_group;" ::: "memory");
}
template <int N>
__device__ __forceinline__ void cp_wait() {
    asm volatile("cp.async.wait_group %0;" ::"n"(N) : "memory");
}

__device__ __forceinline__ void ldmatrix_x4(uint32_t& r0, uint32_t& r1,
                                            uint32_t& r2, uint32_t& r3, uint32_t addr) {
    asm volatile("ldmatrix.sync.aligned.m8n8.x4.shared.b16 {%0,%1,%2,%3}, [%4];"
                 : "=r"(r0), "=r"(r1), "=r"(r2), "=r"(r3) : "r"(addr));
}

__device__ __forceinline__ void mma_f16(float& c0, float& c1, float& c2, float& c3,
                                        uint32_t a0, uint32_t a1, uint32_t a2, uint32_t a3,
                                        uint32_t b0, uint32_t b1) {
    asm volatile(
        "mma.sync.aligned.m16n8k16.row.col.f32.f16.f16.f32 "
        "{%0,%1,%2,%3}, {%4,%5,%6,%7}, {%8,%9}, {%0,%1,%2,%3};"
        : "+f"(c0), "+f"(c1), "+f"(c2), "+f"(c3)
        : "r"(a0), "r"(a1), "r"(a2), "r"(a3), "r"(b0), "r"(b1));
}

// ----------------- pre-kernels: F, W -> fp16 (RNE) -------------------------

__global__ void __launch_bounds__(256) fconv_kernel(const float* __restrict__ F) {
    size_t i = (size_t)blockIdx.x * 256 + threadIdx.x;   // one float4 each
    const float4 v = ((const float4*)F)[i];
    __half2 h0 = __floats2half2_rn(v.x, v.y);
    __half2 h1 = __floats2half2_rn(v.z, v.w);
    ((uint2*)F16)[i] = make_uint2(h2_as_u32(h0), h2_as_u32(h1));
}

__global__ void __launch_bounds__(256) wconv_kernel(const float* __restrict__ W) {
    size_t i = (size_t)blockIdx.x * 256 + threadIdx.x;
    if (i < (size_t)qc::COUT * qc::KTOT / 4) {
        const float4 v = ((const float4*)W)[i];
        __half2 h0 = __floats2half2_rn(v.x, v.y);
        __half2 h1 = __floats2half2_rn(v.z, v.w);
        ((uint2*)W16)[i] = make_uint2(h2_as_u32(h0), h2_as_u32(h1));
    }
}

// ------------------------------- kernel -----------------------------------

__global__ void __launch_bounds__(qc::THREADS, 3)
quadconv_mma_kernel(const int* __restrict__ NIDX,
                    const float* __restrict__ BIAS,
                    float* __restrict__ OUT) {
    using namespace qc;
    extern __shared__ __half smh[];
    const uint32_t sA_u = smem_u32(smh + OFF_A);
    const uint32_t sB_u = smem_u32(smh + OFF_B);

    const int tid  = threadIdx.x;
    const int wid  = tid >> 5;    // 0..3
    const int lane = tid & 31;
    const int g    = lane >> 2;   // 0..7
    const int klo  = lane & 3;    // 0..3
    const int gb   = blockIdx.x * MTILE;

    // ---- per-thread loader coordinates & register-cached indices -----------
    const int lrow = tid >> 2;    // 0..31
    const int lseg = tid & 3;     // 0..3 (8 halves = 16B each)
    int idxr[4];                  // neighbor index for rows lrow+32i, current kn
    auto refresh_idx = [&](int kn) {
#pragma unroll
        for (int i = 0; i < 4; i++)
            idxr[i] = NIDX[(size_t)(gb + lrow + i * 32) * KNB + kn];
    };

    // A gather (zfill OOB) + B (W chunk), both already fp16.
    auto load_tiles = [&](int kb, int buf) {
        const int coff = (kb & 3) * 32;            // halves offset in feature row
#pragma unroll
        for (int i = 0; i < 4; i++) {              // A: 512 chunks / 128 thr
            int row = lrow + i * 32;
            int nb  = idxr[i];
            bool ok = (unsigned)nb < (unsigned)NPTS;
            const __half* src = F16 + (size_t)(ok ? nb : 0) * CIN + coff + lseg * 8;
            cp_async16(sA_u + (uint32_t)(buf * A_HALF + row * ROWPAD + lseg * 8) * 2,
                       src, ok ? 16 : 0);
        }
#pragma unroll
        for (int i = 0; i < 4; i++) {              // B: 512 chunks / 128 thr
            int n = lrow + i * 32;
            const __half* src = W16 + (size_t)n * KTOT + kb * 32 + lseg * 8;
            cp_async16(sB_u + (uint32_t)(buf * B_HALF + n * ROWPAD + lseg * 8) * 2,
                       src, 16);
        }
    };

    // ---- warp tiling: 4 warps 2x2, warp tile 64(M) x 64(N) -----------------
    const int Mbase = (wid >> 1) * 64;
    const int Nbase = (wid & 1) * 64;
    float acc[4][8][4];
#pragma unroll
    for (int mf = 0; mf < 4; mf++)
#pragma unroll
        for (int nf = 0; nf < 8; nf++)
#pragma unroll
            for (int q = 0; q < 4; q++) acc[mf][nf][q] = 0.f;

    // ---- ldmatrix per-lane base offsets (bytes, buffer-relative) -----------
    // A x4: m=lane>>3 -> {r0-7/k0-7, r8-15/k0-7, r0-7/k8-15, r8-15/k8-15}
    const int a_rit = (lane & 7) + ((lane >> 3) & 1) * 8;
    const int a_k8  = (lane >> 4) * 8;             // halves
    uint32_t aoff[4];
#pragma unroll
    for (int mf = 0; mf < 4; mf++)
        aoff[mf] = (uint32_t)(((Mbase + mf * 16 + a_rit) * ROWPAD + a_k8) * 2);
    // B x4 per 16-n pair p: {n0-7/k0-7, n0-7/k8-15, n8-15/k0-7, n8-15/k8-15}
    const int b_nr = ((lane >> 4) & 1) * 8 + (lane & 7);
    const int b_k8 = ((lane >> 3) & 1) * 8;
    uint32_t boff[4];
#pragma unroll
    for (int p = 0; p < 4; p++)
        boff[p] = (uint32_t)(((Nbase + p * 16 + b_nr) * ROWPAD + b_k8) * 2);

    // ---- prologue -----------------------------------------------------------
    refresh_idx(0);
    int kn_cur = 0;
    load_tiles(0, 0);
    cp_commit();

    // ---- main K loop (loads first, then wait, then mma) ---------------------
    for (int kb = 0; kb < NKB; kb++) {
        const int buf = kb & 1;
        const int pf  = kb + 1;
        if (pf < NKB) {
            const int knp = pf >> 2;
            if (knp != kn_cur) { kn_cur = knp; refresh_idx(knp); }
            load_tiles(pf, buf ^ 1);
            cp_commit();
            cp_wait<1>();
        } else {
            cp_wait<0>();
        }
        __syncthreads();   // cross-thread visibility of buf's tiles

        const uint32_t abuf = sA_u + (uint32_t)(buf * A_HALF) * 2;
        const uint32_t bbuf = sB_u + (uint32_t)(buf * B_HALF) * 2;

#pragma unroll
        for (int s = 0; s < 2; s++) {          // 2 k-steps of 16
            uint32_t afr[4][4];
#pragma unroll
            for (int mf = 0; mf < 4; mf++)
                ldmatrix_x4(afr[mf][0], afr[mf][1], afr[mf][2], afr[mf][3],
                            abuf + aoff[mf] + s * 32);   // 16 halves = 32B
            // lazy B: one ldmatrix per 16-n pair, immediately consumed
#pragma unroll
            for (int p = 0; p < 4; p++) {
                uint32_t b0a, b0b, b1a, b1b;   // nf=2p:{b0a,b0b}, nf=2p+1:{b1a,b1b}
                ldmatrix_x4(b0a, b0b, b1a, b1b, bbuf + boff[p] + s * 32);
#pragma unroll
                for (int mf = 0; mf < 4; mf++) {
                    mma_f16(acc[mf][2 * p][0], acc[mf][2 * p][1],
                            acc[mf][2 * p][2], acc[mf][2 * p][3],
                            afr[mf][0], afr[mf][1], afr[mf][2], afr[mf][3],
                            b0a, b0b);
                    mma_f16(acc[mf][2 * p + 1][0], acc[mf][2 * p + 1][1],
                            acc[mf][2 * p + 1][2], acc[mf][2 * p + 1][3],
                            afr[mf][0], afr[mf][1], afr[mf][2], afr[mf][3],
                            b1a, b1b);
                }
            }
        }
        __syncthreads();   // all reads of buf done before kb+2 overwrites it
    }

    // ---- epilogue: add bias (global, L2-hot), float2 stores -----------------
#pragma unroll
    for (int mf = 0; mf < 4; mf++) {
#pragma unroll
        for (int nf = 0; nf < 8; nf++) {
            int col  = Nbase + nf * 8 + 2 * klo;
            float bx = __ldg(BIAS + col), by = __ldg(BIAS + col + 1);
            size_t r0 = (size_t)(gb + Mbase + mf * 16 + g) * COUT + col;
            size_t r1 = r0 + (size_t)8 * COUT;
            float2 v0 = make_float2(acc[mf][nf][0] + bx, acc[mf][nf][1] + by);
            float2 v1 = make_float2(acc[mf][nf][2] + bx, acc[mf][nf][3] + by);
            *(float2*)(OUT + r0) = v0;
            *(float2*)(OUT + r1) = v1;
        }
    }
}

// ----------------------------- launch glue --------------------------------

extern "C" void kernel_launch(void* const* d_in, const int* in_sizes, int n_in,
                              void* d_out, int out_size) {
    using namespace qc;
    const float* F = (const float*)d_in[0];
    const int*   I = (const int*)d_in[1];
    const float* W = (const float*)d_in[2];
    const float* B = (const float*)d_in[3];
    for (int i = 0; i < n_in; i++) {
        switch (in_sizes[i]) {
            case NPTS * CIN:       F = (const float*)d_in[i]; break;      // 33554432
            case NPTS * KNB:       I = (const int*)d_in[i];   break;      // 2359296
            case COUT * KNB * CIN: W = (const float*)d_in[i]; break;      // 147456
            case COUT:             B = (const float*)d_in[i]; break;      // 128
            default: break;
        }
    }
    fconv_kernel<<<(NPTS * CIN / 4) / 256, 256>>>(F);                 // 32768 blocks
    wconv_kernel<<<((COUT * KTOT / 4) + 255) / 256, 256>>>(W);
    cudaFuncSetAttribute(quadconv_mma_kernel,
                         cudaFuncAttributeMaxDynamicSharedMemorySize, SMEM_BYTES);
    quadconv_mma_kernel<<<CTAS, THREADS, SMEM_BYTES>>>(I, B, (float*)d_out);
}

// round 15
// speedup vs baseline: 1.6454x; 1.1054x over previous
#include <cuda_runtime.h>
#include <cuda_fp16.h>
#include <cstdint>

// ---------------------------------------------------------------------------
// QuadConv via baseline-PTX fp16 mma.sync m16n8k16 + ldmatrix (compute_103).
//
//   out[N,128] = concat_k( F[idx[:,k]] ) @ W^T + b
//   N=262144, C_IN=C_OUT=128, K=9 -> GEMM M=N, N=128, K=1152 (A row-gathered).
//   neigh_idx is int32 on the wire.
//
// R14: KB 32 -> 64 per pipeline stage. R13 showed main kernel at 263us vs
// 128us fp16 tensor floor; the gap is per-stage overhead (wait+barrier+load
// burst) paid 36x. Doubling the K-chunk halves the stage count (18) and
// doubles mma work per barrier. smem 72KB/CTA keeps 3 CTAs/SM. Same k
// accumulation order -> rel_err unchanged. F/W pre-converted to fp16 once
// per launch (fconv ~32us, DRAM-bound).
// ---------------------------------------------------------------------------

namespace qc {
constexpr int NPTS   = 262144;
constexpr int CIN    = 128;
constexpr int COUT   = 128;
constexpr int KNB    = 9;
constexpr int KTOT   = KNB * CIN;      // 1152
constexpr int KB     = 64;             // k per pipeline stage
constexpr int NKB    = KTOT / KB;      // 18 stages
constexpr int MTILE  = 128;
constexpr int CTAS   = NPTS / MTILE;   // 2048
constexpr int THREADS = 128;           // 4 warps

constexpr int ROWPAD = 72;             // halves per smem row (64 + 8 pad = 144B)
                                       // ldmatrix phase banks: 36r mod 32 = 4r distinct
constexpr int A_HALF = MTILE * ROWPAD;          // 9216 halves per buffer
constexpr int B_HALF = COUT * ROWPAD;           // 9216
constexpr int OFF_A  = 0;                       // 2 buffers
constexpr int OFF_B  = 2 * A_HALF;              // 2 buffers
constexpr int SMEM_HALVES = OFF_B + 2 * B_HALF; // 36864
constexpr int SMEM_BYTES  = SMEM_HALVES * 2;    // 73,728 -> 3 CTAs/SM
} // namespace qc

// fp16 copies of F and W, produced once per launch by pre-kernels.
__device__ __half F16[qc::NPTS * qc::CIN];      // 64 MB static
__device__ __half W16[qc::COUT * qc::KTOT];     // 288 KB static

// ------------------------------ PTX helpers -------------------------------

__device__ __forceinline__ uint32_t smem_u32(const void* p) {
    return (uint32_t)__cvta_generic_to_shared(p);
}

__device__ __forceinline__ uint32_t h2_as_u32(__half2 h) {
    uint32_t u;
    memcpy(&u, &h, 4);
    return u;
}

__device__ __forceinline__ void cp_async16(uint32_t dst, const void* src, int src_size) {
    asm volatile("cp.async.cg.shared.global [%0], [%1], 16, %2;"
                 ::"r"(dst), "l"(src), "r"(src_size) : "memory");
}
__device__ __forceinline__ void cp_commit() {
    asm volatile("cp.async.commit_group;" ::: "memory");
}
template <int N>
__device__ __forceinline__ void cp_wait() {
    asm volatile("cp.async.wait_group %0;" ::"n"(N) : "memory");
}

__device__ __forceinline__ void ldmatrix_x4(uint32_t& r0, uint32_t& r1,
                                            uint32_t& r2, uint32_t& r3, uint32_t addr) {
    asm volatile("ldmatrix.sync.aligned.m8n8.x4.shared.b16 {%0,%1,%2,%3}, [%4];"
                 : "=r"(r0), "=r"(r1), "=r"(r2), "=r"(r3) : "r"(addr));
}

__device__ __forceinline__ void mma_f16(float& c0, float& c1, float& c2, float& c3,
                                        uint32_t a0, uint32_t a1, uint32_t a2, uint32_t a3,
                                        uint32_t b0, uint32_t b1) {
    asm volatile(
        "mma.sync.aligned.m16n8k16.row.col.f32.f16.f16.f32 "
        "{%0,%1,%2,%3}, {%4,%5,%6,%7}, {%8,%9}, {%0,%1,%2,%3};"
        : "+f"(c0), "+f"(c1), "+f"(c2), "+f"(c3)
        : "r"(a0), "r"(a1), "r"(a2), "r"(a3), "r"(b0), "r"(b1));
}

// ----------------- pre-kernels: F, W -> fp16 (RNE) -------------------------

__global__ void __launch_bounds__(256) fconv_kernel(const float* __restrict__ F) {
    size_t i = (size_t)blockIdx.x * 256 + threadIdx.x;   // one float4 each
    const float4 v = ((const float4*)F)[i];
    __half2 h0 = __floats2half2_rn(v.x, v.y);
    __half2 h1 = __floats2half2_rn(v.z, v.w);
    ((uint2*)F16)[i] = make_uint2(h2_as_u32(h0), h2_as_u32(h1));
}

__global__ void __launch_bounds__(256) wconv_kernel(const float* __restrict__ W) {
    size_t i = (size_t)blockIdx.x * 256 + threadIdx.x;
    if (i < (size_t)qc::COUT * qc::KTOT / 4) {
        const float4 v = ((const float4*)W)[i];
        __half2 h0 = __floats2half2_rn(v.x, v.y);
        __half2 h1 = __floats2half2_rn(v.z, v.w);
        ((uint2*)W16)[i] = make_uint2(h2_as_u32(h0), h2_as_u32(h1));
    }
}

// ------------------------------- kernel -----------------------------------

__global__ void __launch_bounds__(qc::THREADS, 3)
quadconv_mma_kernel(const int* __restrict__ NIDX,
                    const float* __restrict__ BIAS,
                    float* __restrict__ OUT) {
    using namespace qc;
    extern __shared__ __half smh[];
    const uint32_t sA_u = smem_u32(smh + OFF_A);
    const uint32_t sB_u = smem_u32(smh + OFF_B);

    const int tid  = threadIdx.x;
    const int wid  = tid >> 5;    // 0..3
    const int lane = tid & 31;
    const int g    = lane >> 2;   // 0..7
    const int klo  = lane & 3;    // 0..3
    const int gb   = blockIdx.x * MTILE;

    // ---- per-thread loader coordinates & register-cached indices -----------
    // KB=64 halves per row per stage = 128B = 8 chunks of 16B.
    const int lrow = tid >> 3;    // 0..15
    const int lseg = tid & 7;     // 0..7
    int idxr[8];                  // neighbor index for rows lrow+16i, current kn
    auto refresh_idx = [&](int kn) {
#pragma unroll
        for (int i = 0; i < 8; i++)
            idxr[i] = NIDX[(size_t)(gb + lrow + i * 16) * KNB + kn];
    };

    // A gather (zfill OOB) + B (W chunk), both already fp16.
    // kb indexes 64-wide K chunks; neighbor kn = kb>>1, col offset = (kb&1)*64.
    auto load_tiles = [&](int kb, int buf) {
        const int coff = (kb & 1) * 64;            // halves offset in feature row
#pragma unroll
        for (int i = 0; i < 8; i++) {              // A: 1024 chunks / 128 thr
            int row = lrow + i * 16;
            int nb  = idxr[i];
            bool ok = (unsigned)nb < (unsigned)NPTS;
            const __half* src = F16 + (size_t)(ok ? nb : 0) * CIN + coff + lseg * 8;
            cp_async16(sA_u + (uint32_t)(buf * A_HALF + row * ROWPAD + lseg * 8) * 2,
                       src, ok ? 16 : 0);
        }
#pragma unroll
        for (int i = 0; i < 8; i++) {              // B: 1024 chunks / 128 thr
            int n = lrow + i * 16;
            const __half* src = W16 + (size_t)n * KTOT + kb * 64 + lseg * 8;
            cp_async16(sB_u + (uint32_t)(buf * B_HALF + n * ROWPAD + lseg * 8) * 2,
                       src, 16);
        }
    };

    // ---- warp tiling: 4 warps 2x2, warp tile 64(M) x 64(N) -----------------
    const int Mbase = (wid >> 1) * 64;
    const int Nbase = (wid & 1) * 64;
    float acc[4][8][4];
#pragma unroll
    for (int mf = 0; mf < 4; mf++)
#pragma unroll
        for (int nf = 0; nf < 8; nf++)
#pragma unroll
            for (int q = 0; q < 4; q++) acc[mf][nf][q] = 0.f;

    // ---- ldmatrix per-lane base offsets (bytes, buffer-relative) -----------
    // A x4: m=lane>>3 -> {r0-7/k0-7, r8-15/k0-7, r0-7/k8-15, r8-15/k8-15}
    const int a_rit = (lane & 7) + ((lane >> 3) & 1) * 8;
    const int a_k8  = (lane >> 4) * 8;             // halves
    uint32_t aoff[4];
#pragma unroll
    for (int mf = 0; mf < 4; mf++)
        aoff[mf] = (uint32_t)(((Mbase + mf * 16 + a_rit) * ROWPAD + a_k8) * 2);
    // B x4 per 16-n pair p: {n0-7/k0-7, n0-7/k8-15, n8-15/k0-7, n8-15/k8-15}
    const int b_nr = ((lane >> 4) & 1) * 8 + (lane & 7);
    const int b_k8 = ((lane >> 3) & 1) * 8;
    uint32_t boff[4];
#pragma unroll
    for (int p = 0; p < 4; p++)
        boff[p] = (uint32_t)(((Nbase + p * 16 + b_nr) * ROWPAD + b_k8) * 2);

    // ---- prologue -----------------------------------------------------------
    refresh_idx(0);
    int kn_cur = 0;
    load_tiles(0, 0);
    cp_commit();

    // ---- main K loop (loads first, then wait, then mma) ---------------------
    for (int kb = 0; kb < NKB; kb++) {
        const int buf = kb & 1;
        const int pf  = kb + 1;
        if (pf < NKB) {
            const int knp = pf >> 1;
            if (knp != kn_cur) { kn_cur = knp; refresh_idx(knp); }
            load_tiles(pf, buf ^ 1);
            cp_commit();
            cp_wait<1>();
        } else {
            cp_wait<0>();
        }
        __syncthreads();   // cross-thread visibility of buf's tiles

        const uint32_t abuf = sA_u + (uint32_t)(buf * A_HALF) * 2;
        const uint32_t bbuf = sB_u + (uint32_t)(buf * B_HALF) * 2;

#pragma unroll
        for (int s = 0; s < 4; s++) {          // 4 k-steps of 16
            uint32_t afr[4][4];
#pragma unroll
            for (int mf = 0; mf < 4; mf++)
                ldmatrix_x4(afr[mf][0], afr[mf][1], afr[mf][2], afr[mf][3],
                            abuf + aoff[mf] + s * 32);   // 16 halves = 32B
            // lazy B: one ldmatrix per 16-n pair, immediately consumed
#pragma unroll
            for (int p = 0; p < 4; p++) {
                uint32_t b0a, b0b, b1a, b1b;   // nf=2p:{b0a,b0b}, nf=2p+1:{b1a,b1b}
                ldmatrix_x4(b0a, b0b, b1a, b1b, bbuf + boff[p] + s * 32);
#pragma unroll
                for (int mf = 0; mf < 4; mf++) {
                    mma_f16(acc[mf][2 * p][0], acc[mf][2 * p][1],
                            acc[mf][2 * p][2], acc[mf][2 * p][3],
                            afr[mf][0], afr[mf][1], afr[mf][2], afr[mf][3],
                            b0a, b0b);
                    mma_f16(acc[mf][2 * p + 1][0], acc[mf][2 * p + 1][1],
                            acc[mf][2 * p + 1][2], acc[mf][2 * p + 1][3],
                            afr[mf][0], afr[mf][1], afr[mf][2], afr[mf][3],
                            b1a, b1b);
                }
            }
        }
        __syncthreads();   // all reads of buf done before kb+2 overwrites it
    }

    // ---- epilogue: add bias (global, L2-hot), float2 stores -----------------
#pragma unroll
    for (int mf = 0; mf < 4; mf++) {
#pragma unroll
        for (int nf = 0; nf < 8; nf++) {
            int col  = Nbase + nf * 8 + 2 * klo;
            float bx = __ldg(BIAS + col), by = __ldg(BIAS + col + 1);
            size_t r0 = (size_t)(gb + Mbase + mf * 16 + g) * COUT + col;
            size_t r1 = r0 + (size_t)8 * COUT;
            float2 v0 = make_float2(acc[mf][nf][0] + bx, acc[mf][nf][1] + by);
            float2 v1 = make_float2(acc[mf][nf][2] + bx, acc[mf][nf][3] + by);
            *(float2*)(OUT + r0) = v0;
            *(float2*)(OUT + r1) = v1;
        }
    }
}

// ----------------------------- launch glue --------------------------------

extern "C" void kernel_launch(void* const* d_in, const int* in_sizes, int n_in,
                              void* d_out, int out_size) {
    using namespace qc;
    const float* F = (const float*)d_in[0];
    const int*   I = (const int*)d_in[1];
    const float* W = (const float*)d_in[2];
    const float* B = (const float*)d_in[3];
    for (int i = 0; i < n_in; i++) {
        switch (in_sizes[i]) {
            case NPTS * CIN:       F = (const float*)d_in[i]; break;      // 33554432
            case NPTS * KNB:       I = (const int*)d_in[i];   break;      // 2359296
            case COUT * KNB * CIN: W = (const float*)d_in[i]; break;      // 147456
            case COUT:             B = (const float*)d_in[i]; break;      // 128
            default: break;
        }
    }
    fconv_kernel<<<(NPTS * CIN / 4) / 256, 256>>>(F);                 // 32768 blocks
    wconv_kernel<<<((COUT * KTOT / 4) + 255) / 256, 256>>>(W);
    cudaFuncSetAttribute(quadconv_mma_kernel,
                         cudaFuncAttributeMaxDynamicSharedMemorySize, SMEM_BYTES);
    quadconv_mma_kernel<<<CTAS, THREADS, SMEM_BYTES>>>(I, B, (float*)d_out);
}